// round 5
// baseline (speedup 1.0000x reference)
#include <cuda_runtime.h>
#include <cstdint>
#include <cstddef>

// Problem constants
#define BB 8
#define CCT 128
#define HH 128
#define WW 128
#define RR 4
#define NOFF 81

// Tiling
#define TH 8
#define TW 32
#define NGROUP 9
#define NT (NGROUP * 32)      // 288 threads
#define CCH 8                 // channels per chunk
#define NCHUNK (CCT / CCH)    // 16
#define NBUF 3                // triple buffer -> 1 barrier/chunk

// Shared layout (floats)
#define FSTR 36
#define SSTR 44
#define SROWS 16
#define F_CH_FLOATS (TH * FSTR)           // 288
#define S_CH_FLOATS (SROWS * SSTR)        // 704
#define F_BUF_FLOATS (CCH * F_CH_FLOATS)  // 2304
#define S_BUF_FLOATS (CCH * S_CH_FLOATS)  // 5632
#define F_OFF 0
#define S_OFF (NBUF * F_BUF_FLOATS)       // 6912
#define SMEM_FLOATS (S_OFF + NBUF * S_BUF_FLOATS)   // 23808
#define SMEM_BYTES (SMEM_FLOATS * 4)      // 95232  (x2 CTAs = 186KB/SM)

#define NS_SLOTS (CCH * SROWS * 10)       // 1280
#define NF_SLOTS (CCH * TH * 8)           // 512
#define KS 5
#define KF 2
#define CH_STRIDE_E (CCH * HH * WW)       // u32-safe element stride per chunk

typedef unsigned long long u64;

__device__ __forceinline__ u64 pk2(float lo, float hi) {
    u64 r;
    asm("mov.b64 %0, {%1, %2};" : "=l"(r) : "f"(lo), "f"(hi));
    return r;
}
__device__ __forceinline__ float lo_f(u64 v) { return __uint_as_float((unsigned)v); }
__device__ __forceinline__ float hi_f(u64 v) { return __uint_as_float((unsigned)(v >> 32)); }

__device__ __forceinline__ void fma2(u64& d, u64 a, u64 b) {
    asm("fma.rn.f32x2 %0, %1, %2, %0;" : "+l"(d) : "l"(a), "l"(b));
}
__device__ __forceinline__ void cpa16(float* dst, const float* src) {
    unsigned s = (unsigned)__cvta_generic_to_shared(dst);
    asm volatile("cp.async.ca.shared.global [%0], [%1], 16;" :: "r"(s), "l"(src));
}

__global__ void __launch_bounds__(NT, 2)
costvol_kernel(const float* __restrict__ first,
               const float* __restrict__ second,
               float* __restrict__ out) {
    extern __shared__ __align__(16) float smem[];

    const int tid = threadIdx.x;
    const int g   = tid >> 5;          // dy index 0..8
    const int lid = tid & 31;
    const int lh  = lid >> 2;          // local row 0..7
    const int lw  = (lid & 3) << 3;    // local col base {0,8,16,24}

    const int w0 = blockIdx.x * TW;
    const int h0 = blockIdx.y * TH;
    const int bz = blockIdx.z;

    const size_t batch_off = (size_t)bz * CCT * HH * WW;
    const float* firstB  = first  + batch_off;
    const float* secondB = second + batch_off;

    // ---------- precompute loader slots (u32 offsets; validity chunk-invariant) ----------
    unsigned s_off[KS], s_dst[KS];
    bool     s_val[KS];
#pragma unroll
    for (int k = 0; k < KS; k++) {
        int s = tid + k * NT;
        bool v = (s < NS_SLOTS);
        int ss = v ? s : 0;
        int ch  = ss / 160;
        int rem = ss - ch * 160;
        int r   = rem / 10;
        int j   = rem - r * 10;
        int gh = h0 - RR + r;
        int gw = w0 - RR + 4 * j;
        v = v && ((unsigned)gh < (unsigned)HH) && ((unsigned)gw < (unsigned)WW);
        s_val[k] = v;
        s_off[k] = (unsigned)((ch * HH + gh) * WW + gw);
        s_dst[k] = (unsigned)((ch * SROWS + r) * SSTR + 4 * j);
    }
    unsigned f_off[KF], f_dst[KF];
    bool     f_val[KF];
#pragma unroll
    for (int k = 0; k < KF; k++) {
        int s = tid + k * NT;
        bool v = (s < NF_SLOTS);
        int ss = v ? s : 0;
        int ch = ss >> 6;
        int r  = (ss >> 3) & 7;
        int j  = ss & 7;
        f_val[k] = v;
        f_off[k] = (unsigned)((ch * HH + (h0 + r)) * WW + (w0 + 4 * j));
        f_dst[k] = (unsigned)((ch * TH + r) * FSTR + 4 * j);
    }

    // ---------- zero-prefill (halo written once, never touched again) ----------
    for (int i = tid * 4; i < SMEM_FLOATS; i += NT * 4)
        *(float4*)(smem + i) = make_float4(0.f, 0.f, 0.f, 0.f);
    __syncthreads();

    // ---------- chunk issuer ----------
    auto issue = [&](int buf) {
        float* sbase = smem + S_OFF + buf * S_BUF_FLOATS;
        float* fbase = smem + F_OFF + buf * F_BUF_FLOATS;
#pragma unroll
        for (int k = 0; k < KS; k++) {
            if (s_val[k]) cpa16(sbase + s_dst[k], secondB + s_off[k]);
            s_off[k] += CH_STRIDE_E;
        }
#pragma unroll
        for (int k = 0; k < KF; k++) {
            if (f_val[k]) cpa16(fbase + f_dst[k], firstB + f_off[k]);
            f_off[k] += CH_STRIDE_E;
        }
        asm volatile("cp.async.commit_group;" ::: "memory");
    };

    issue(0);
    issue(1);

    // ---------- accumulators ----------
    u64 accE[5][4];           // even dx = 2e; pixel pairs (0,1)(2,3)(4,5)(6,7)
    u64 accO[4][3];           // odd dx = 2o+1; pixel pairs (1,2)(3,4)(5,6)
    float acc0[4], acc7[4];   // odd-dx boundary pixels 0 and 7
#pragma unroll
    for (int e = 0; e < 5; e++)
#pragma unroll
        for (int p = 0; p < 4; p++) accE[e][p] = 0ULL;
#pragma unroll
    for (int o = 0; o < 4; o++) {
#pragma unroll
        for (int p = 0; p < 3; p++) accO[o][p] = 0ULL;
        acc0[o] = 0.f; acc7[o] = 0.f;
    }

    const float* Fbase = smem + F_OFF + lh * FSTR + lw;
    const float* Sbase = smem + S_OFF + (lh + g) * SSTR + lw;

    // one chunk: wait, barrier, prefetch-issue, FMA over CCH channels
    auto step = [&](int cc, int buf) {
        if (cc + 1 < NCHUNK)
            asm volatile("cp.async.wait_group 1;" ::: "memory");
        else
            asm volatile("cp.async.wait_group 0;" ::: "memory");
        __syncthreads();
        if (cc + 2 < NCHUNK) issue((cc + 2) % NBUF);

        const float* Fp = Fbase + buf * F_BUF_FLOATS;
        const float* Sp = Sbase + buf * S_BUF_FLOATS;

#pragma unroll
        for (int ch = 0; ch < CCH; ch++) {
            const float* fptr = Fp + ch * F_CH_FLOATS;
            const float* sptr = Sp + ch * S_CH_FLOATS;

            // first: 4 aligned pairs + scalar views
            ulonglong2 fA = *(const ulonglong2*)fptr;
            ulonglong2 fB = *(const ulonglong2*)(fptr + 4);
            u64 fp0 = fA.x, fp1 = fA.y, fp2 = fB.x, fp3 = fB.y;
            float f0 = lo_f(fp0), f1 = hi_f(fp0);
            float f2 = lo_f(fp1), f3 = hi_f(fp1);
            float f4 = lo_f(fp2), f5 = hi_f(fp2);
            float f6 = lo_f(fp3), f7 = hi_f(fp3);
            u64 op0 = pk2(f1, f2);
            u64 op1 = pk2(f3, f4);
            u64 op2 = pk2(f5, f6);

            // second window: 8 aligned pairs (16 floats)
            ulonglong2 wA = *(const ulonglong2*)sptr;
            ulonglong2 wB = *(const ulonglong2*)(sptr + 4);
            ulonglong2 wC = *(const ulonglong2*)(sptr + 8);
            ulonglong2 wD = *(const ulonglong2*)(sptr + 12);
            u64 wp[8] = { wA.x, wA.y, wB.x, wB.y, wC.x, wC.y, wD.x, wD.y };

            // even dx = 2e: all operands aligned, zero packs
#pragma unroll
            for (int e = 0; e < 5; e++) {
                fma2(accE[e][0], fp0, wp[0 + e]);
                fma2(accE[e][1], fp1, wp[1 + e]);
                fma2(accE[e][2], fp2, wp[2 + e]);
                fma2(accE[e][3], fp3, wp[3 + e]);
            }
            // odd dx = 2o+1: window pairs aligned; 3 first-packs reused
#pragma unroll
            for (int o = 0; o < 4; o++) {
                fma2(accO[o][0], op0, wp[o + 1]);
                fma2(accO[o][1], op1, wp[o + 2]);
                fma2(accO[o][2], op2, wp[o + 3]);
                acc0[o] = fmaf(f0, hi_f(wp[o]),     acc0[o]);   // w[2o+1]
                acc7[o] = fmaf(f7, lo_f(wp[o + 4]), acc7[o]);   // w[8+2o]
            }
        }
    };

#pragma unroll 1
    for (int base = 0; base < NCHUNK; base += 3) {
        step(base, 0);
        if (base + 1 < NCHUNK) step(base + 1, 1);
        if (base + 2 < NCHUNK) step(base + 2, 2);
    }

    // ---------- store: mean over C ----------
    const float inv = 1.0f / (float)CCT;
    const size_t row_base = ((size_t)bz * NOFF) * HH * WW
                          + (size_t)(h0 + lh) * WW + (w0 + lw);
#pragma unroll
    for (int e = 0; e < 5; e++) {
        int o = g * 9 + 2 * e;
        float* op = out + row_base + (size_t)o * HH * WW;
        float4 v0 = make_float4(lo_f(accE[e][0]) * inv, hi_f(accE[e][0]) * inv,
                                lo_f(accE[e][1]) * inv, hi_f(accE[e][1]) * inv);
        float4 v1 = make_float4(lo_f(accE[e][2]) * inv, hi_f(accE[e][2]) * inv,
                                lo_f(accE[e][3]) * inv, hi_f(accE[e][3]) * inv);
        *(float4*)op       = v0;
        *(float4*)(op + 4) = v1;
    }
#pragma unroll
    for (int o2 = 0; o2 < 4; o2++) {
        int o = g * 9 + 2 * o2 + 1;
        float* op = out + row_base + (size_t)o * HH * WW;
        float4 v0 = make_float4(acc0[o2] * inv,
                                lo_f(accO[o2][0]) * inv, hi_f(accO[o2][0]) * inv,
                                lo_f(accO[o2][1]) * inv);
        float4 v1 = make_float4(hi_f(accO[o2][1]) * inv,
                                lo_f(accO[o2][2]) * inv, hi_f(accO[o2][2]) * inv,
                                acc7[o2] * inv);
        *(float4*)op       = v0;
        *(float4*)(op + 4) = v1;
    }
}

extern "C" void kernel_launch(void* const* d_in, const int* in_sizes, int n_in,
                              void* d_out, int out_size) {
    const float* first  = (const float*)d_in[0];
    const float* second = (const float*)d_in[1];
    float* out = (float*)d_out;

    cudaFuncSetAttribute(costvol_kernel,
                         cudaFuncAttributeMaxDynamicSharedMemorySize, SMEM_BYTES);

    dim3 grid(WW / TW, HH / TH, BB);   // (4,16,8) = 512 blocks
    costvol_kernel<<<grid, NT, SMEM_BYTES>>>(first, second, out);
}

// round 6
// speedup vs baseline: 1.1997x; 1.1997x over previous
#include <cuda_runtime.h>
#include <cstdint>
#include <cstddef>

// Problem constants
#define BB 8
#define CCT 128
#define HH 128
#define WW 128
#define RR 4
#define NOFF 81

// Tiling: 8x32 pixel tile, 4 px/thread, 64 threads per dy-group, 9 groups
#define TH 8
#define TW 32
#define PX 4
#define NGROUP 9
#define NT (NGROUP * 64)      // 576 threads, 18 warps
#define CCH 8                 // channels per chunk
#define NCHUNK (CCT / CCH)    // 16
#define NBUF 3                // triple buffer -> 1 barrier/chunk

// Shared layout (floats)
#define FSTR 36
#define SSTR 44
#define SROWS 16
#define F_CH_FLOATS (TH * FSTR)           // 288
#define S_CH_FLOATS (SROWS * SSTR)        // 704
#define F_BUF_FLOATS (CCH * F_CH_FLOATS)  // 2304
#define S_BUF_FLOATS (CCH * S_CH_FLOATS)  // 5632
#define F_OFF 0
#define S_OFF (NBUF * F_BUF_FLOATS)       // 6912
#define SMEM_FLOATS (S_OFF + NBUF * S_BUF_FLOATS)   // 23808
#define SMEM_BYTES (SMEM_FLOATS * 4)      // 95232 (1 CTA/SM)

#define NS_SLOTS (CCH * SROWS * 10)       // 1280
#define NF_SLOTS (CCH * TH * 8)           // 512
#define KS 3
#define CH_STRIDE_E (CCH * HH * WW)       // u32-safe element stride per chunk

typedef unsigned long long u64;

__device__ __forceinline__ u64 pk2(float lo, float hi) {
    u64 r;
    asm("mov.b64 %0, {%1, %2};" : "=l"(r) : "f"(lo), "f"(hi));
    return r;
}
__device__ __forceinline__ float lo_f(u64 v) { return __uint_as_float((unsigned)v); }
__device__ __forceinline__ float hi_f(u64 v) { return __uint_as_float((unsigned)(v >> 32)); }

__device__ __forceinline__ void fma2(u64& d, u64 a, u64 b) {
    asm("fma.rn.f32x2 %0, %1, %2, %0;" : "+l"(d) : "l"(a), "l"(b));
}
__device__ __forceinline__ void cpa16(float* dst, const float* src) {
    unsigned s = (unsigned)__cvta_generic_to_shared(dst);
    asm volatile("cp.async.ca.shared.global [%0], [%1], 16;" :: "r"(s), "l"(src));
}

__global__ void __launch_bounds__(NT, 1)
costvol_kernel(const float* __restrict__ first,
               const float* __restrict__ second,
               float* __restrict__ out) {
    extern __shared__ __align__(16) float smem[];

    const int tid = threadIdx.x;
    const int g   = tid / 64;            // dy index 0..8
    const int lid = tid & 63;
    const int lh  = lid >> 3;            // local row 0..7
    const int lw  = (lid & 7) << 2;      // local col base {0,4,...,28}

    const int w0 = blockIdx.x * TW;
    const int h0 = blockIdx.y * TH;
    const int bz = blockIdx.z;

    const size_t batch_off = (size_t)bz * CCT * HH * WW;
    const float* firstB  = first  + batch_off;
    const float* secondB = second + batch_off;

    // ---------- precompute loader slots (u32 offsets; validity chunk-invariant) ----------
    unsigned s_off[KS], s_dst[KS];
    bool     s_val[KS];
#pragma unroll
    for (int k = 0; k < KS; k++) {
        int s = tid + k * NT;
        bool v = (s < NS_SLOTS);
        int ss = v ? s : 0;
        int ch  = ss / 160;
        int rem = ss - ch * 160;
        int r   = rem / 10;
        int j   = rem - r * 10;
        int gh = h0 - RR + r;
        int gw = w0 - RR + 4 * j;
        v = v && ((unsigned)gh < (unsigned)HH) && ((unsigned)gw < (unsigned)WW);
        s_val[k] = v;
        s_off[k] = (unsigned)((ch * HH + gh) * WW + gw);
        s_dst[k] = (unsigned)((ch * SROWS + r) * SSTR + 4 * j);
    }
    unsigned f_off, f_dst;
    {
        int ss = (tid < NF_SLOTS) ? tid : 0;
        int ch = ss >> 6;
        int r  = (ss >> 3) & 7;
        int j  = ss & 7;
        f_off = (unsigned)((ch * HH + (h0 + r)) * WW + (w0 + 4 * j));
        f_dst = (unsigned)((ch * TH + r) * FSTR + 4 * j);
    }
    const bool f_val = (tid < NF_SLOTS);

    // ---------- zero-prefill (halo written once, never touched again) ----------
    for (int i = tid * 4; i < SMEM_FLOATS; i += NT * 4)
        *(float4*)(smem + i) = make_float4(0.f, 0.f, 0.f, 0.f);
    __syncthreads();

    // ---------- chunk issuer ----------
    auto issue = [&](int buf) {
        float* sbase = smem + S_OFF + buf * S_BUF_FLOATS;
        float* fbase = smem + F_OFF + buf * F_BUF_FLOATS;
#pragma unroll
        for (int k = 0; k < KS; k++) {
            if (s_val[k]) cpa16(sbase + s_dst[k], secondB + s_off[k]);
            s_off[k] += CH_STRIDE_E;
        }
        if (f_val) cpa16(fbase + f_dst, firstB + f_off);
        f_off += CH_STRIDE_E;
        asm volatile("cp.async.commit_group;" ::: "memory");
    };

    issue(0);
    issue(1);

    // ---------- accumulators ----------
    u64 accE[5][2];           // even dx = 2e; pixel pairs (0,1)(2,3)
    u64 accO[4];              // odd dx = 2o+1; pixel pair (1,2)
    float acc0[4], acc3[4];   // odd-dx boundary pixels 0 and 3
#pragma unroll
    for (int e = 0; e < 5; e++) { accE[e][0] = 0ULL; accE[e][1] = 0ULL; }
#pragma unroll
    for (int o = 0; o < 4; o++) { accO[o] = 0ULL; acc0[o] = 0.f; acc3[o] = 0.f; }

    const float* Fbase = smem + F_OFF + lh * FSTR + lw;
    const float* Sbase = smem + S_OFF + (lh + g) * SSTR + lw;

    // one chunk: wait, barrier, prefetch-issue, FMA over CCH channels
    auto step = [&](int cc, int buf) {
        if (cc + 1 < NCHUNK)
            asm volatile("cp.async.wait_group 1;" ::: "memory");
        else
            asm volatile("cp.async.wait_group 0;" ::: "memory");
        __syncthreads();
        if (cc + 2 < NCHUNK) issue((cc + 2) % NBUF);

        const float* Fp = Fbase + buf * F_BUF_FLOATS;
        const float* Sp = Sbase + buf * S_BUF_FLOATS;

#pragma unroll
        for (int ch = 0; ch < CCH; ch++) {
            const float* fptr = Fp + ch * F_CH_FLOATS;
            const float* sptr = Sp + ch * S_CH_FLOATS;

            // first: 2 aligned pairs + scalar views; 1 odd-pack
            ulonglong2 fA = *(const ulonglong2*)fptr;
            u64 fp0 = fA.x, fp1 = fA.y;
            float f0 = lo_f(fp0), f1 = hi_f(fp0);
            float f2 = lo_f(fp1), f3 = hi_f(fp1);
            u64 op0 = pk2(f1, f2);

            // second window: 12 floats = 6 aligned pairs
            ulonglong2 wA = *(const ulonglong2*)sptr;
            ulonglong2 wB = *(const ulonglong2*)(sptr + 4);
            ulonglong2 wC = *(const ulonglong2*)(sptr + 8);
            u64 wp[6] = { wA.x, wA.y, wB.x, wB.y, wC.x, wC.y };

            // even dx = 2e: aligned, zero packs
#pragma unroll
            for (int e = 0; e < 5; e++) {
                fma2(accE[e][0], fp0, wp[e]);
                fma2(accE[e][1], fp1, wp[e + 1]);
            }
            // odd dx = 2o+1: middle pair aligned; boundary scalars
#pragma unroll
            for (int o = 0; o < 4; o++) {
                fma2(accO[o], op0, wp[o + 1]);
                acc0[o] = fmaf(f0, hi_f(wp[o]),     acc0[o]);   // w[2o+1]
                acc3[o] = fmaf(f3, lo_f(wp[o + 2]), acc3[o]);   // w[2o+4]
            }
        }
    };

#pragma unroll 1
    for (int base = 0; base < NCHUNK; base += 3) {
        step(base, 0);
        if (base + 1 < NCHUNK) step(base + 1, 1);
        if (base + 2 < NCHUNK) step(base + 2, 2);
    }

    // ---------- store: mean over C ----------
    const float inv = 1.0f / (float)CCT;
    const size_t row_base = ((size_t)bz * NOFF) * HH * WW
                          + (size_t)(h0 + lh) * WW + (w0 + lw);
#pragma unroll
    for (int e = 0; e < 5; e++) {
        int o = g * 9 + 2 * e;
        float* op = out + row_base + (size_t)o * HH * WW;
        *(float4*)op = make_float4(lo_f(accE[e][0]) * inv, hi_f(accE[e][0]) * inv,
                                   lo_f(accE[e][1]) * inv, hi_f(accE[e][1]) * inv);
    }
#pragma unroll
    for (int o2 = 0; o2 < 4; o2++) {
        int o = g * 9 + 2 * o2 + 1;
        float* op = out + row_base + (size_t)o * HH * WW;
        *(float4*)op = make_float4(acc0[o2] * inv,
                                   lo_f(accO[o2]) * inv, hi_f(accO[o2]) * inv,
                                   acc3[o2] * inv);
    }
}

extern "C" void kernel_launch(void* const* d_in, const int* in_sizes, int n_in,
                              void* d_out, int out_size) {
    const float* first  = (const float*)d_in[0];
    const float* second = (const float*)d_in[1];
    float* out = (float*)d_out;

    cudaFuncSetAttribute(costvol_kernel,
                         cudaFuncAttributeMaxDynamicSharedMemorySize, SMEM_BYTES);

    dim3 grid(WW / TW, HH / TH, BB);   // (4,16,8) = 512 blocks
    costvol_kernel<<<grid, NT, SMEM_BYTES>>>(first, second, out);
}